// round 3
// baseline (speedup 1.0000x reference)
#include <cuda_runtime.h>
#include <cstdint>

// Problem constants
#define B_ 128
#define N_ 2048
#define D_ 128
#define H_ 8
#define SROW 2056            // padded scores row stride (floats): (8h+n)%32 distinct banks
#define NTHREADS 256
#define TILE 32
#define NTILES (N_ / TILE)

// Shared memory layout (bytes):
//   [0,       65792)  scores: 8 * 2056 floats   (also aliased for phase A/B/C/D scratch)
//   [65792,   69888)  qk:     1024 floats       (reused as s_inv after phase F)
//   [69888,  102656)  x tiles: 2 * 32 * 128 floats (double buffer)
#define SMEM_BYTES (65792 + 4096 + 32768)

__device__ __forceinline__ void cp16(uint32_t saddr, const void* gaddr) {
    asm volatile("cp.async.cg.shared.global [%0], [%1], 16;" :: "r"(saddr), "l"(gaddr));
}

extern "C" __global__ void __launch_bounds__(NTHREADS, 1)
actor_kernel(const float* __restrict__ x,
             const int* __restrict__ first_node,     // harness stores int64 as int32
             const int* __restrict__ current_node,
             const void* __restrict__ mask_raw,      // bool -> int32 (likely) or uint8
             const float* __restrict__ W_lin,
             const float* __restrict__ b_lin,
             const float* __restrict__ Wq,
             const float* __restrict__ bq,
             const float* __restrict__ Wk,
             const float* __restrict__ bk,
             float* __restrict__ out)
{
    extern __shared__ char smem[];
    float*  s_scores = (float*)smem;                     // 8 x 2056
    float*  s_qk     = (float*)(smem + 65792);           // 8 x 128
    float4* s_xt4    = (float4*)(smem + 69888);          // 2 x 1024 float4

    // scratch aliases inside the scores region (all dead before phase F writes scores)
    float4* s_red4 = (float4*)s_scores;                  // 256 float4  (floats [0,1024))
    float*  s_ctx  = s_scores + 1024;                    // 384
    float*  s_qin  = s_scores + 1024 + 384;              // 128
    float*  s_q    = s_scores + 1024 + 512;              // 128
    float*  s_bias = s_scores + 1024 + 640;              // 8
    float*  s_inv  = s_qk;                               // 8 (reuse qk space after phase F)

    const int b    = blockIdx.x;
    const int t    = threadIdx.x;
    const int lane = t & 31;
    const int w    = t >> 5;

    const float*  xb  = x + (size_t)b * (N_ * D_);
    const float4* xb4 = (const float4*)xb;

    // ---------------- Phase 0: sniff mask storage dtype ----------------
    // int32 storage holds only 0/1 words; byte-packed bools produce words >1
    // (e.g. 0x00000101) with probability ~1 over 2048 random 0/1-byte words.
    int mask_is_u8;
    {
        const uint32_t* mw = (const uint32_t*)mask_raw;
        int pred = 0;
        #pragma unroll
        for (int i = t; i < 2048; i += NTHREADS) pred |= (mw[i] > 1u);
        mask_is_u8 = __syncthreads_or(pred);
    }

    // ---------------- Phase A: graph_emb = mean over N (column means) ----------------
    {
        float4 acc = make_float4(0.f, 0.f, 0.f, 0.f);
        #pragma unroll 4
        for (int i = t; i < N_ * D_ / 4; i += NTHREADS) {
            float4 v = xb4[i];
            acc.x += v.x; acc.y += v.y; acc.z += v.z; acc.w += v.w;
        }
        s_red4[t] = acc;
    }
    __syncthreads();
    if (t < 32) {
        float4 s = s_red4[t];
        #pragma unroll
        for (int m = 1; m < 8; ++m) {
            float4 v = s_red4[t + 32 * m];
            s.x += v.x; s.y += v.y; s.z += v.z; s.w += v.w;
        }
        const float inv = 1.0f / (float)N_;
        s_ctx[4 * t + 0] = s.x * inv;
        s_ctx[4 * t + 1] = s.y * inv;
        s_ctx[4 * t + 2] = s.z * inv;
        s_ctx[4 * t + 3] = s.w * inv;
    }

    // ---------------- Phase B: gather first/current node features ----------------
    {
        int fn = first_node[b];
        int cn = current_node[b];
        fn = min(max(fn, 0), N_ - 1);   // crash-guard
        cn = min(max(cn, 0), N_ - 1);
        if (t < 128) s_ctx[128 + t]         = xb[(size_t)fn * D_ + t];
        else         s_ctx[256 + (t - 128)] = xb[(size_t)cn * D_ + (t - 128)];
    }
    __syncthreads();

    // ---------------- Phase C: q_in[d] = ctx . W_lin[d,:] + b_lin[d] ----------------
    if (t < 128) {
        const float4* wr = (const float4*)(W_lin + t * 384);
        const float4* c4 = (const float4*)s_ctx;
        float a0 = 0.f, a1 = 0.f;
        #pragma unroll 8
        for (int j = 0; j < 96; j += 2) {
            float4 wv = wr[j],   cv = c4[j];
            a0 += wv.x * cv.x + wv.y * cv.y + wv.z * cv.z + wv.w * cv.w;
            float4 wv2 = wr[j + 1], cv2 = c4[j + 1];
            a1 += wv2.x * cv2.x + wv2.y * cv2.y + wv2.z * cv2.z + wv2.w * cv2.w;
        }
        s_qin[t] = a0 + a1 + b_lin[t];
    }
    __syncthreads();

    // ---------------- Phase D: q[d] = q_in . Wq[d,:] + bq[d] ----------------
    if (t < 128) {
        const float4* wr = (const float4*)(Wq + t * 128);
        const float4* c4 = (const float4*)s_qin;
        float a0 = 0.f, a1 = 0.f;
        #pragma unroll 8
        for (int j = 0; j < 32; j += 2) {
            float4 wv = wr[j],   cv = c4[j];
            a0 += wv.x * cv.x + wv.y * cv.y + wv.z * cv.z + wv.w * cv.w;
            float4 wv2 = wr[j + 1], cv2 = c4[j + 1];
            a1 += wv2.x * cv2.x + wv2.y * cv2.y + wv2.z * cv2.z + wv2.w * cv2.w;
        }
        s_q[t] = a0 + a1 + bq[t];
    }
    __syncthreads();

    // ---------------- Phase E: qk[h,c] = 0.25 * sum_j q[h*16+j] * Wk[h*16+j, c] ----------------
    if (t < 128) {
        #pragma unroll
        for (int h = 0; h < H_; ++h) {
            float a = 0.f;
            #pragma unroll
            for (int j = 0; j < 16; ++j)
                a += s_q[h * 16 + j] * Wk[(h * 16 + j) * 128 + t];
            s_qk[h * 128 + t] = a * 0.25f;
        }
        if (t < 8) {
            float a = 0.f;
            #pragma unroll
            for (int j = 0; j < 16; ++j)
                a += s_q[t * 16 + j] * bk[t * 16 + j];
            s_bias[t] = a * 0.25f;
        }
    }
    __syncthreads();

    // ---------------- Phase F: scores[h,n] = x[n,:] . qk[h,:] + bias[h], masked ----------------
    const int  qq = lane & 3;
    const int  hh = lane >> 2;
    float qkr[32];
    {
        const float4* qk4 = (const float4*)(s_qk + hh * 128);
        #pragma unroll
        for (int j = 0; j < 8; ++j) {
            float4 v = qk4[qq + 4 * j];
            qkr[4 * j + 0] = v.x; qkr[4 * j + 1] = v.y;
            qkr[4 * j + 2] = v.z; qkr[4 * j + 3] = v.w;
        }
    }
    const float sbias = s_bias[hh];
    const unsigned char* mb_u8  = (const unsigned char*)mask_raw + (size_t)b * N_;
    const int*           mb_i32 = (const int*)mask_raw + (size_t)b * N_;
    const uint32_t xt_base = (uint32_t)__cvta_generic_to_shared(s_xt4);

    // prefetch tile 0
    {
        #pragma unroll
        for (int kk = 0; kk < 4; ++kk) {
            int j = t + NTHREADS * kk;
            cp16(xt_base + (uint32_t)j * 16u, xb4 + j);
        }
        asm volatile("cp.async.commit_group;");
    }

    for (int tt = 0; tt < NTILES; ++tt) {
        const int buf = tt & 1;
        if (tt + 1 < NTILES) {
            const int nb = 1 - buf;
            #pragma unroll
            for (int kk = 0; kk < 4; ++kk) {
                int j = t + NTHREADS * kk;
                cp16(xt_base + (uint32_t)(nb * 1024 + j) * 16u,
                     xb4 + (size_t)(tt + 1) * 1024 + j);
            }
            asm volatile("cp.async.commit_group;");
            asm volatile("cp.async.wait_group 1;");
        } else {
            asm volatile("cp.async.wait_group 0;");
        }
        __syncthreads();

        const float4* xr0 = s_xt4 + buf * 1024;
        #pragma unroll
        for (int r = 0; r < 4; ++r) {
            const int nl = w * 4 + r;          // warp w owns rows 4w..4w+3
            const int n  = tt * TILE + nl;
            const float4* xr = xr0 + nl * 32;
            float a0 = 0.f, a1 = 0.f, a2 = 0.f, a3 = 0.f;
            #pragma unroll
            for (int j = 0; j < 8; ++j) {
                float4 xv = xr[qq + 4 * j];
                a0 += xv.x * qkr[4 * j + 0];
                a1 += xv.y * qkr[4 * j + 1];
                a2 += xv.z * qkr[4 * j + 2];
                a3 += xv.w * qkr[4 * j + 3];
            }
            float s = (a0 + a1) + (a2 + a3);
            s += __shfl_xor_sync(0xffffffffu, s, 1);
            s += __shfl_xor_sync(0xffffffffu, s, 2);
            if (qq == 0) {
                const bool masked = mask_is_u8 ? (mb_u8[n] != 0) : (mb_i32[n] != 0);
                s_scores[hh * SROW + n] = masked ? -INFINITY : (s + sbias);
            }
        }
        __syncthreads();
    }

    // ---------------- Phase G: per-head softmax (warp w owns head w) ----------------
    {
        float* sr = s_scores + w * SROW;
        float mx = -INFINITY;
        for (int i = lane; i < N_; i += 32) mx = fmaxf(mx, sr[i]);
        #pragma unroll
        for (int o = 16; o > 0; o >>= 1) mx = fmaxf(mx, __shfl_xor_sync(0xffffffffu, mx, o));
        float sum = 0.f;
        for (int i = lane; i < N_; i += 32) {
            float e = __expf(sr[i] - mx);
            sr[i] = e;
            sum += e;
        }
        #pragma unroll
        for (int o = 16; o > 0; o >>= 1) sum += __shfl_xor_sync(0xffffffffu, sum, o);
        if (lane == 0) s_inv[w] = 1.0f / sum;
    }
    __syncthreads();

    // ---------------- Phase H: out[b,n] = mean_h attn[h,n] ----------------
    {
        float invh[H_];
        #pragma unroll
        for (int h = 0; h < H_; ++h) invh[h] = s_inv[h] * 0.125f;
        float* ob = out + (size_t)b * N_;
        for (int i = t; i < N_ / 4; i += NTHREADS) {
            float4 o = make_float4(0.f, 0.f, 0.f, 0.f);
            #pragma unroll
            for (int h = 0; h < H_; ++h) {
                float4 v = *(const float4*)(s_scores + h * SROW + 4 * i);
                o.x += v.x * invh[h]; o.y += v.y * invh[h];
                o.z += v.z * invh[h]; o.w += v.w * invh[h];
            }
            ((float4*)ob)[i] = o;
        }
    }
}

extern "C" void kernel_launch(void* const* d_in, const int* in_sizes, int n_in,
                              void* d_out, int out_size)
{
    const float* x      = (const float*)d_in[0];
    const int*   fn     = (const int*)d_in[1];
    const int*   cn     = (const int*)d_in[2];
    const void*  mask   = d_in[3];
    const float* W_lin  = (const float*)d_in[4];
    const float* b_lin  = (const float*)d_in[5];
    const float* Wq     = (const float*)d_in[6];
    const float* bq     = (const float*)d_in[7];
    const float* Wk     = (const float*)d_in[8];
    const float* bk     = (const float*)d_in[9];

    cudaFuncSetAttribute(actor_kernel,
                         cudaFuncAttributeMaxDynamicSharedMemorySize, SMEM_BYTES);
    actor_kernel<<<B_, NTHREADS, SMEM_BYTES>>>(x, fn, cn, mask, W_lin, b_lin,
                                               Wq, bq, Wk, bk, (float*)d_out);
}

// round 4
// speedup vs baseline: 1.0726x; 1.0726x over previous
#include <cuda_runtime.h>
#include <cstdint>

#define B_ 128
#define N_ 2048
#define D_ 128
#define H_ 8
#define SPLITS 8               // kernel B: N-splits per batch
#define QK_STRIDE 1032         // 8*128 qk + 8 bias per batch

typedef unsigned long long ull;

// Device scratch (allocation-free contract: __device__ globals)
__device__ float g_qk[B_ * QK_STRIDE];          // per-batch folded qk + bias
__device__ float g_scores[B_ * N_ * H_];        // [b][n][h] masked raw scores (8 MB)
__device__ int   g_mask_u8;                     // 1 if mask stored as bytes, 0 if int32

__device__ __forceinline__ void fma2(ull& d, ull a, ull b) {
    asm("fma.rn.f32x2 %0, %1, %2, %0;" : "+l"(d) : "l"(a), "l"(b));
}
__device__ __forceinline__ float lo32(ull v) { return __uint_as_float((unsigned)v); }
__device__ __forceinline__ float hi32(ull v) { return __uint_as_float((unsigned)(v >> 32)); }

// ======================= Kernel A: mean + context -> qk =======================
extern "C" __global__ void __launch_bounds__(1024, 1)
kA(const float* __restrict__ x,
   const int* __restrict__ first_node,
   const int* __restrict__ current_node,
   const void* __restrict__ mask_raw,
   const float* __restrict__ W_lin,
   const float* __restrict__ b_lin,
   const float* __restrict__ Wq,
   const float* __restrict__ bq,
   const float* __restrict__ Wk,
   const float* __restrict__ bk)
{
    __shared__ __align__(16) float4 s_red4[1024];     // 16 KB
    __shared__ __align__(16) float  s_ctx[384];
    __shared__ __align__(16) float  s_qin[128];
    __shared__ __align__(16) float  s_q[128];

    const int b = blockIdx.x;
    const int t = threadIdx.x;
    const float*  xb  = x + (size_t)b * (N_ * D_);
    const float4* xb4 = (const float4*)xb;

    // --- mask dtype sniff (block 0 only): int32 bools are only 0/1 words ---
    if (b == 0) {
        const uint32_t* mw = (const uint32_t*)mask_raw;
        int pred = 0;
        for (int i = t; i < 2048; i += 1024) pred |= (mw[i] > 1u);
        int r = __syncthreads_or(pred);
        if (t == 0) g_mask_u8 = r;
    }

    // --- column mean over N (thread t holds cols 4*(t&31)..+3) ---
    {
        float4 acc = make_float4(0.f, 0.f, 0.f, 0.f);
        #pragma unroll 8
        for (int i = t; i < N_ * D_ / 4; i += 1024) {
            float4 v = xb4[i];
            acc.x += v.x; acc.y += v.y; acc.z += v.z; acc.w += v.w;
        }
        s_red4[t] = acc;
    }
    __syncthreads();
    if (t < 32) {
        float4 s = s_red4[t];
        #pragma unroll
        for (int m = 1; m < 32; ++m) {
            float4 v = s_red4[t + 32 * m];
            s.x += v.x; s.y += v.y; s.z += v.z; s.w += v.w;
        }
        const float inv = 1.0f / (float)N_;
        s_ctx[4 * t + 0] = s.x * inv;
        s_ctx[4 * t + 1] = s.y * inv;
        s_ctx[4 * t + 2] = s.z * inv;
        s_ctx[4 * t + 3] = s.w * inv;
    }

    // --- gather first/current node rows ---
    {
        int fn = first_node[b];
        int cn = current_node[b];
        fn = min(max(fn, 0), N_ - 1);
        cn = min(max(cn, 0), N_ - 1);
        if (t < 128)      s_ctx[128 + t]         = xb[(size_t)fn * D_ + t];
        else if (t < 256) s_ctx[256 + (t - 128)] = xb[(size_t)cn * D_ + (t - 128)];
    }
    __syncthreads();

    // --- q_in = ctx . W_lin^T + b_lin ---
    if (t < 128) {
        const float4* wr = (const float4*)(W_lin + t * 384);
        const float4* c4 = (const float4*)s_ctx;
        float a0 = 0.f, a1 = 0.f;
        #pragma unroll 8
        for (int j = 0; j < 96; j += 2) {
            float4 wv = wr[j],     cv = c4[j];
            a0 += wv.x * cv.x + wv.y * cv.y + wv.z * cv.z + wv.w * cv.w;
            float4 wv2 = wr[j + 1], cv2 = c4[j + 1];
            a1 += wv2.x * cv2.x + wv2.y * cv2.y + wv2.z * cv2.z + wv2.w * cv2.w;
        }
        s_qin[t] = a0 + a1 + b_lin[t];
    }
    __syncthreads();

    // --- q = q_in . Wq^T + bq ---
    if (t < 128) {
        const float4* wr = (const float4*)(Wq + t * 128);
        const float4* c4 = (const float4*)s_qin;
        float a0 = 0.f, a1 = 0.f;
        #pragma unroll 8
        for (int j = 0; j < 32; j += 2) {
            float4 wv = wr[j],     cv = c4[j];
            a0 += wv.x * cv.x + wv.y * cv.y + wv.z * cv.z + wv.w * cv.w;
            float4 wv2 = wr[j + 1], cv2 = c4[j + 1];
            a1 += wv2.x * cv2.x + wv2.y * cv2.y + wv2.z * cv2.z + wv2.w * cv2.w;
        }
        s_q[t] = a0 + a1 + bq[t];
    }
    __syncthreads();

    // --- qk[h,c] = 0.25 * sum_j q[16h+j] Wk[16h+j, c]; bias[h] = 0.25 * q_h . bk_h ---
    if (t < 128) {
        float* qkb = g_qk + (size_t)b * QK_STRIDE;
        #pragma unroll
        for (int h = 0; h < H_; ++h) {
            float a = 0.f;
            #pragma unroll
            for (int j = 0; j < 16; ++j)
                a += s_q[h * 16 + j] * Wk[(h * 16 + j) * 128 + t];
            qkb[h * 128 + t] = a * 0.25f;
        }
        if (t < 8) {
            float a = 0.f;
            #pragma unroll
            for (int j = 0; j < 16; ++j)
                a += s_q[t * 16 + j] * bk[t * 16 + j];
            qkb[1024 + t] = a * 0.25f;
        }
    }
}

// ======================= Kernel B: scores =======================
// grid = B_ * SPLITS, block = 256. Warp w handles 32 rows; 4 lanes per head.
extern "C" __global__ void __launch_bounds__(256)
kB(const float* __restrict__ x,
   const void* __restrict__ mask_raw)
{
    const int b    = blockIdx.x >> 3;
    const int sp   = blockIdx.x & (SPLITS - 1);
    const int t    = threadIdx.x;
    const int lane = t & 31;
    const int w    = t >> 5;
    const int qq   = lane & 3;
    const int hh   = lane >> 2;

    const float* qkb = g_qk + (size_t)b * QK_STRIDE;

    // lane's 32 qk values as 16 packed f32x2
    ull qkr2[16];
    {
        const ulonglong2* q2 = (const ulonglong2*)(qkb + hh * 128);
        #pragma unroll
        for (int j = 0; j < 8; ++j) {
            ulonglong2 v = q2[qq + 4 * j];
            qkr2[2 * j + 0] = v.x;
            qkr2[2 * j + 1] = v.y;
        }
    }
    const float sbias = qkb[1024 + hh];

    const int mu8 = g_mask_u8;
    const unsigned char* mb8  = (const unsigned char*)mask_raw + (size_t)b * N_;
    const int*           mb32 = (const int*)mask_raw + (size_t)b * N_;

    const float4* xb4 = (const float4*)(x + (size_t)b * (N_ * D_));
    float* sc = g_scores + (size_t)b * (N_ * H_);

    const int n0 = sp * (N_ / SPLITS) + w * 32;
    #pragma unroll 2
    for (int r = 0; r < 32; ++r) {
        const int n = n0 + r;
        const ulonglong2* xr = (const ulonglong2*)(xb4 + (size_t)n * 32);
        ull a0 = 0, a1 = 0, a2 = 0, a3 = 0;
        #pragma unroll
        for (int j = 0; j < 8; j += 2) {
            ulonglong2 xv0 = xr[qq + 4 * j];
            ulonglong2 xv1 = xr[qq + 4 * (j + 1)];
            fma2(a0, xv0.x, qkr2[2 * j + 0]);
            fma2(a1, xv0.y, qkr2[2 * j + 1]);
            fma2(a2, xv1.x, qkr2[2 * j + 2]);
            fma2(a3, xv1.y, qkr2[2 * j + 3]);
        }
        float s = (lo32(a0) + hi32(a0)) + (lo32(a1) + hi32(a1))
                + (lo32(a2) + hi32(a2)) + (lo32(a3) + hi32(a3));
        s += __shfl_xor_sync(0xffffffffu, s, 1);
        s += __shfl_xor_sync(0xffffffffu, s, 2);
        if (qq == 0) {
            const bool masked = mu8 ? (mb8[n] != 0) : (mb32[n] != 0);
            sc[(size_t)n * H_ + hh] = masked ? -INFINITY : (s + sbias);
        }
    }
}

// ======================= Kernel C: softmax + head mean =======================
// grid = B_, block = 256, dynamic smem = (2048*9 + 8) floats
#define KC_SMEM_FLOATS (N_ * 9 + 8)
extern "C" __global__ void __launch_bounds__(256)
kC(float* __restrict__ out)
{
    extern __shared__ float s[];                 // [n][9] padded + inv[8]
    float* s_inv = s + N_ * 9;

    const int b    = blockIdx.x;
    const int t    = threadIdx.x;
    const int lane = t & 31;
    const int w    = t >> 5;

    // load scores [n][8] -> smem stride 9
    const float4* in4 = (const float4*)(g_scores + (size_t)b * (N_ * H_));
    for (int i = t; i < N_ * H_ / 4; i += 256) {
        float4 v = in4[i];
        const int n  = i >> 1;
        const int h0 = (i & 1) * 4;
        float* d = s + n * 9 + h0;
        d[0] = v.x; d[1] = v.y; d[2] = v.z; d[3] = v.w;
    }
    __syncthreads();

    // per-head softmax: warp w owns head w
    {
        float mx = -INFINITY;
        for (int i = lane; i < N_; i += 32) mx = fmaxf(mx, s[i * 9 + w]);
        #pragma unroll
        for (int o = 16; o > 0; o >>= 1) mx = fmaxf(mx, __shfl_xor_sync(0xffffffffu, mx, o));
        float sum = 0.f;
        for (int i = lane; i < N_; i += 32) {
            float e = __expf(s[i * 9 + w] - mx);
            s[i * 9 + w] = e;
            sum += e;
        }
        #pragma unroll
        for (int o = 16; o > 0; o >>= 1) sum += __shfl_xor_sync(0xffffffffu, sum, o);
        if (lane == 0) s_inv[w] = 1.0f / sum;
    }
    __syncthreads();

    // out[b,n] = (1/8) sum_h e[n,h] * inv[h]
    float invh[H_];
    #pragma unroll
    for (int h = 0; h < H_; ++h) invh[h] = s_inv[h] * 0.125f;
    float* ob = out + (size_t)b * N_;
    #pragma unroll 2
    for (int n = t; n < N_; n += 256) {
        const float* rr = s + n * 9;
        float a = 0.f;
        #pragma unroll
        for (int h = 0; h < H_; ++h) a += rr[h] * invh[h];
        ob[n] = a;
    }
}

extern "C" void kernel_launch(void* const* d_in, const int* in_sizes, int n_in,
                              void* d_out, int out_size)
{
    const float* x      = (const float*)d_in[0];
    const int*   fn     = (const int*)d_in[1];
    const int*   cn     = (const int*)d_in[2];
    const void*  mask   = d_in[3];
    const float* W_lin  = (const float*)d_in[4];
    const float* b_lin  = (const float*)d_in[5];
    const float* Wq     = (const float*)d_in[6];
    const float* bq     = (const float*)d_in[7];
    const float* Wk     = (const float*)d_in[8];
    const float* bk     = (const float*)d_in[9];

    cudaFuncSetAttribute(kC, cudaFuncAttributeMaxDynamicSharedMemorySize,
                         KC_SMEM_FLOATS * (int)sizeof(float));

    kA<<<B_, 1024>>>(x, fn, cn, mask, W_lin, b_lin, Wq, bq, Wk, bk);
    kB<<<B_ * SPLITS, 256>>>(x, mask);
    kC<<<B_, 256, KC_SMEM_FLOATS * sizeof(float)>>>((float*)d_out);
}